// round 1
// baseline (speedup 1.0000x reference)
#include <cuda_runtime.h>
#include <math.h>

// OneClassLoss on GB300.
// Pipeline (all on default stream, graph-capturable, no allocs):
//   K1 fft_psd : per image-pair 2D FFT |X|^2 accumulation + input norms
//   K2 gram    : K-split fp32 rank-1-update partial Gram (256 blocks x K=64)
//   K3 dist    : reduce gram partials -> Dist matrix
//   K4 psdred  : reduce psd partials -> per-block (sum log, sum avg)
//   K5 final   : log-softmax CE + psd scalar -> out[0]

#define NPIX 16384   // 128*128
#define NB_GRAM 256  // gram K-chunks (K=64 each)

__device__ float g_psd[128 * NPIX];            // per-pair |X|^2 sums (x1[b]+x2[b])
__device__ float g_gram_part[NB_GRAM * NPIX];  // partial Gram per K-chunk
__device__ float g_norm[256];                  // ||a_i||^2 (0..127), ||b_j||^2 (128..255)
__device__ float g_dist[NPIX];                 // Dist matrix
__device__ float g_red[128];                   // [0..63] sum(log(avg)), [64..127] sum(avg)

// ---------------------------------------------------------------------------
// 128-point DIF radix-2 FFT, one warp, 4 complex values/lane.
// Storage index n = r*32 + lane. Output is bit-reversed (permutation is
// irrelevant: psd statistics are bin-permutation invariant).
// tw[k] = exp(-2*pi*i*k/128), k=0..63 (in shared memory).
// ---------------------------------------------------------------------------
__device__ __forceinline__ void fft128(float vr[4], float vi[4],
                                       const float2* __restrict__ tw, int lane) {
    // stage h=64: pairs (n, n+64) -> (r, r+2), twiddle W_128^n
    #pragma unroll
    for (int r = 0; r < 2; r++) {
        float2 w = tw[r * 32 + lane];
        float ur = vr[r], ui = vi[r], xr = vr[r + 2], xi = vi[r + 2];
        vr[r] = ur + xr; vi[r] = ui + xi;
        float dr = ur - xr, di = ui - xi;
        vr[r + 2] = dr * w.x - di * w.y;
        vi[r + 2] = dr * w.y + di * w.x;
    }
    // stage h=32: pairs (r,r+1) within each 64-block, twiddle W_128^(2*lane)
    {
        float2 w = tw[2 * lane];
        #pragma unroll
        for (int half = 0; half < 2; half++) {
            int r = half * 2;
            float ur = vr[r], ui = vi[r], xr = vr[r + 1], xi = vi[r + 1];
            vr[r] = ur + xr; vi[r] = ui + xi;
            float dr = ur - xr, di = ui - xi;
            vr[r + 1] = dr * w.x - di * w.y;
            vi[r + 1] = dr * w.y + di * w.x;
        }
    }
    // cross-lane stages h = 16, 8, 4, 2, 1
    #pragma unroll
    for (int st = 0; st < 5; st++) {
        const int h = 16 >> st;
        const int k = (lane & (h - 1)) * (64 / h);
        float2 w = tw[k];
        bool hiLane = (lane & h) != 0;
        #pragma unroll
        for (int r = 0; r < 4; r++) {
            float ar = vr[r], ai = vi[r];
            float br = __shfl_xor_sync(0xffffffffu, ar, h);
            float bi = __shfl_xor_sync(0xffffffffu, ai, h);
            if (hiLane) {
                float dr = br - ar, di = bi - ai;  // u - v
                vr[r] = dr * w.x - di * w.y;
                vi[r] = dr * w.y + di * w.x;
            } else {
                vr[r] = ar + br;
                vi[r] = ai + bi;
            }
        }
    }
}

// ---------------------------------------------------------------------------
// K1: one block per image pair b: (x1[b], x2[b]).
// Row FFTs -> smem (padded 129 stride, conflict-free column reads),
// column FFTs -> |X|^2 accumulated in registers across both images.
// Also computes input norms (free: we load the images anyway).
// psd bin layout = col*128 + p (coalesced writes; permutation irrelevant).
// ---------------------------------------------------------------------------
__global__ __launch_bounds__(512, 1)
void fft_psd_kernel(const float* __restrict__ x1, const float* __restrict__ x2) {
    extern __shared__ float smem[];
    float*  s_re = smem;                         // 128*129
    float*  s_im = smem + 128 * 129;             // 128*129
    float2* s_tw = (float2*)(smem + 2 * 128 * 129);  // 64 twiddles
    __shared__ float s_red[16];

    int t = threadIdx.x, lane = t & 31, warp = t >> 5;  // 16 warps
    int b = blockIdx.x;

    if (t < 64) {
        float ang = -6.283185307179586f * (float)t / 128.0f;
        float sn, cs;
        sincosf(ang, &sn, &cs);
        s_tw[t] = make_float2(cs, sn);
    }

    float pacc[8][4];
    #pragma unroll
    for (int q = 0; q < 8; q++)
        #pragma unroll
        for (int r = 0; r < 4; r++) pacc[q][r] = 0.f;

    __syncthreads();

    for (int s = 0; s < 2; s++) {
        const float* img = (s == 0 ? x1 : x2) + (size_t)b * NPIX;
        float nrm = 0.f;

        // ---- row pass: warp handles rows q*16+warp ----
        for (int q = 0; q < 8; q++) {
            int row = q * 16 + warp;
            float vr[4], vi[4];
            #pragma unroll
            for (int r = 0; r < 4; r++) {
                float x = img[row * 128 + r * 32 + lane];
                vr[r] = x; vi[r] = 0.f;
                nrm += x * x;
            }
            fft128(vr, vi, s_tw, lane);
            #pragma unroll
            for (int r = 0; r < 4; r++) {
                s_re[row * 129 + r * 32 + lane] = vr[r];
                s_im[row * 129 + r * 32 + lane] = vi[r];
            }
        }

        // ---- norm reduce (also the barrier between row stores / col loads) ----
        #pragma unroll
        for (int o = 16; o; o >>= 1) nrm += __shfl_xor_sync(0xffffffffu, nrm, o);
        if (lane == 0) s_red[warp] = nrm;
        __syncthreads();
        if (t == 0) {
            float tot = 0.f;
            for (int w = 0; w < 16; w++) tot += s_red[w];
            g_norm[s * 128 + b] = tot;
        }

        // ---- column pass: warp handles cols q*16+warp ----
        for (int q = 0; q < 8; q++) {
            int col = q * 16 + warp;
            float vr[4], vi[4];
            #pragma unroll
            for (int r = 0; r < 4; r++) {
                vr[r] = s_re[(r * 32 + lane) * 129 + col];
                vi[r] = s_im[(r * 32 + lane) * 129 + col];
            }
            fft128(vr, vi, s_tw, lane);
            #pragma unroll
            for (int r = 0; r < 4; r++)
                pacc[q][r] += vr[r] * vr[r] + vi[r] * vi[r];
        }
        __syncthreads();  // before next image overwrites smem
    }

    float* psd = g_psd + (size_t)b * NPIX;
    for (int q = 0; q < 8; q++) {
        int col = q * 16 + warp;
        #pragma unroll
        for (int r = 0; r < 4; r++)
            psd[col * 128 + r * 32 + lane] = pacc[q][r];  // coalesced per (q,r)
    }
}

// ---------------------------------------------------------------------------
// K2: partial Gram. Block kb covers K chunk [kb*64, kb*64+64).
// 256 threads, each computes an 8x8 microtile via rank-1 updates from smem.
// ---------------------------------------------------------------------------
__global__ __launch_bounds__(256, 2)
void gram_kernel(const float* __restrict__ A, const float* __restrict__ B) {
    __shared__ float aT[32 * 132];
    __shared__ float bT[32 * 132];
    int t = threadIdx.x, kb = blockIdx.x;
    int i0 = (t >> 4) << 3, j0 = (t & 15) << 3;

    float acc[8][8];
    #pragma unroll
    for (int u = 0; u < 8; u++)
        #pragma unroll
        for (int v = 0; v < 8; v++) acc[u][v] = 0.f;

    for (int stg = 0; stg < 2; stg++) {
        int k0 = kb * 64 + stg * 32;
        __syncthreads();
        #pragma unroll
        for (int v = 0; v < 16; v++) {
            int id = t + (v << 8);
            int row = id >> 5, kk = id & 31;
            aT[kk * 132 + row] = A[(size_t)row * NPIX + k0 + kk];
            bT[kk * 132 + row] = B[(size_t)row * NPIX + k0 + kk];
        }
        __syncthreads();
        #pragma unroll 4
        for (int kk = 0; kk < 32; kk++) {
            float4 a0 = *(const float4*)&aT[kk * 132 + i0];
            float4 a1 = *(const float4*)&aT[kk * 132 + i0 + 4];
            float4 b0 = *(const float4*)&bT[kk * 132 + j0];
            float4 b1 = *(const float4*)&bT[kk * 132 + j0 + 4];
            float av[8] = {a0.x, a0.y, a0.z, a0.w, a1.x, a1.y, a1.z, a1.w};
            float bv[8] = {b0.x, b0.y, b0.z, b0.w, b1.x, b1.y, b1.z, b1.w};
            #pragma unroll
            for (int u = 0; u < 8; u++)
                #pragma unroll
                for (int v = 0; v < 8; v++)
                    acc[u][v] = fmaf(av[u], bv[v], acc[u][v]);
        }
    }

    float* out = g_gram_part + (size_t)kb * NPIX;
    #pragma unroll
    for (int u = 0; u < 8; u++) {
        *(float4*)&out[(i0 + u) * 128 + j0] =
            make_float4(acc[u][0], acc[u][1], acc[u][2], acc[u][3]);
        *(float4*)&out[(i0 + u) * 128 + j0 + 4] =
            make_float4(acc[u][4], acc[u][5], acc[u][6], acc[u][7]);
    }
}

// ---------------------------------------------------------------------------
// K3: reduce gram partials -> Dist.
// ---------------------------------------------------------------------------
__global__ __launch_bounds__(256)
void dist_kernel() {
    int e = blockIdx.x * 256 + threadIdx.x;
    float s = 0.f;
    #pragma unroll 8
    for (int p = 0; p < NB_GRAM; p++) s += g_gram_part[(size_t)p * NPIX + e];
    int i = e >> 7, j = e & 127;
    float d2 = g_norm[i] + g_norm[128 + j] - 2.f * s;
    g_dist[e] = sqrtf(fmaxf(d2, 0.f));
}

// ---------------------------------------------------------------------------
// K4: reduce psd partials; per-block partial of sum(log(avg)) and sum(avg).
// ---------------------------------------------------------------------------
__global__ __launch_bounds__(256)
void psd_reduce_kernel() {
    __shared__ float sbuf[16];
    int t = threadIdx.x, lane = t & 31, warp = t >> 5;
    int e = blockIdx.x * 256 + t;
    float s = 0.f;
    #pragma unroll 8
    for (int p = 0; p < 128; p++) s += g_psd[(size_t)p * NPIX + e];
    float avg = s * (1.f / 256.f);  // 256 total images
    float lg = logf(avg);
    float v1 = lg, v2 = avg;
    #pragma unroll
    for (int o = 16; o; o >>= 1) {
        v1 += __shfl_xor_sync(0xffffffffu, v1, o);
        v2 += __shfl_xor_sync(0xffffffffu, v2, o);
    }
    if (lane == 0) { sbuf[warp] = v1; sbuf[8 + warp] = v2; }
    __syncthreads();
    if (t == 0) {
        float l = 0.f, a = 0.f;
        for (int w = 0; w < 8; w++) { l += sbuf[w]; a += sbuf[8 + w]; }
        g_red[blockIdx.x] = l;
        g_red[64 + blockIdx.x] = a;
    }
}

// ---------------------------------------------------------------------------
// K5: CE over log_softmax rows + psd scalar -> output.
// ---------------------------------------------------------------------------
__global__ __launch_bounds__(128)
void final_kernel(float* __restrict__ out) {
    __shared__ float sbuf[4];
    int t = threadIdx.x, lane = t & 31, warp = t >> 5;
    const float* row = g_dist + t * 128;
    float m = -1e30f;
    for (int j = 0; j < 128; j++) m = fmaxf(m, row[j]);
    float se = 0.f;
    for (int j = 0; j < 128; j++) se += expf(row[j] - m);
    float c = row[t] - (m + logf(se));  // log_probs[t][t]
    #pragma unroll
    for (int o = 16; o; o >>= 1) c += __shfl_xor_sync(0xffffffffu, c, o);
    if (lane == 0) sbuf[warp] = c;
    __syncthreads();
    if (t == 0) {
        float cs = sbuf[0] + sbuf[1] + sbuf[2] + sbuf[3];
        float ce = -cs / 128.f;
        float lsum = 0.f, asum = 0.f;
        for (int w = 0; w < 64; w++) { lsum += g_red[w]; asum += g_red[64 + w]; }
        float r = lsum / 16384.f - logf(asum / 16384.f);
        out[0] = ce - 0.1f * r;
    }
}

// ---------------------------------------------------------------------------
extern "C" void kernel_launch(void* const* d_in, const int* in_sizes, int n_in,
                              void* d_out, int out_size) {
    const float* x1 = (const float*)d_in[0];
    const float* x2 = (const float*)d_in[1];
    float* out = (float*)d_out;

    const int SMEM_FFT = (2 * 128 * 129) * 4 + 64 * 8;  // 132608 B
    cudaFuncSetAttribute(fft_psd_kernel,
                         cudaFuncAttributeMaxDynamicSharedMemorySize, SMEM_FFT);

    fft_psd_kernel<<<128, 512, SMEM_FFT>>>(x1, x2);
    gram_kernel<<<NB_GRAM, 256>>>(x1, x2);
    dist_kernel<<<64, 256>>>();
    psd_reduce_kernel<<<64, 256>>>();
    final_kernel<<<1, 128>>>(out);
}

// round 2
// speedup vs baseline: 1.5514x; 1.5514x over previous
#include <cuda_runtime.h>
#include <math.h>

// OneClassLoss on GB300 — R2.
//  Stream A (legacy): K1 fft_psd (256 blocks, 1 img each, Hermitian-halved cols)
//                     -> psd_partial -> psd_final
//  Stream B (s1):     gram (128 K-chunks) -> dist_partial -> [wait fft] dist_final
//  Join:              final (CE + psd scalar)
// psd statistic is invariant under bin permutation; real rows give
// X[r,128-k] = conj(X[r,k]) so column 128-k's psd bins are a permutation of
// column k's -> compute cols 0..64 only, weight cols 1..63 by 2.

#define NPIX 16384   // 128*128
#define NCOL 65      // retained spectral columns 0..64
#define NBIN (NCOL * 128)
#define NB_GRAM 128  // gram K-chunks (K=128 each)

__device__ float g_psd[256 * NBIN];            // per-image |X|^2 (8.5 MB)
__device__ float g_ptmp[8 * NBIN];             // psd partial sums
__device__ float g_gram_part[NB_GRAM * NPIX];  // partial Gram (8 MB)
__device__ float g_dtmp[8 * NPIX];             // dist partial sums
__device__ float g_norm[256];                  // ||a_i||^2, ||b_j||^2
__device__ float g_dist[NPIX];                 // Dist matrix
__device__ float g_redL[NCOL];                 // per-col weighted sum log(avg)
__device__ float g_redA[NCOL];                 // per-col weighted sum avg

// ---------------------------------------------------------------------------
// 128-point DIF radix-2 FFT, one warp, 4 complex values/lane.
// Input natural order (n = r*32+lane); output slot p holds bin rev7(p).
// ---------------------------------------------------------------------------
__device__ __forceinline__ void fft128(float vr[4], float vi[4],
                                       const float2* __restrict__ tw, int lane) {
    #pragma unroll
    for (int r = 0; r < 2; r++) {  // h=64
        float2 w = tw[r * 32 + lane];
        float ur = vr[r], ui = vi[r], xr = vr[r + 2], xi = vi[r + 2];
        vr[r] = ur + xr; vi[r] = ui + xi;
        float dr = ur - xr, di = ui - xi;
        vr[r + 2] = dr * w.x - di * w.y;
        vi[r + 2] = dr * w.y + di * w.x;
    }
    {  // h=32
        float2 w = tw[2 * lane];
        #pragma unroll
        for (int half = 0; half < 2; half++) {
            int r = half * 2;
            float ur = vr[r], ui = vi[r], xr = vr[r + 1], xi = vi[r + 1];
            vr[r] = ur + xr; vi[r] = ui + xi;
            float dr = ur - xr, di = ui - xi;
            vr[r + 1] = dr * w.x - di * w.y;
            vi[r + 1] = dr * w.y + di * w.x;
        }
    }
    #pragma unroll
    for (int st = 0; st < 5; st++) {  // h = 16,8,4,2,1 cross-lane
        const int h = 16 >> st;
        const int k = (lane & (h - 1)) * (64 / h);
        float2 w = tw[k];
        bool hiLane = (lane & h) != 0;
        #pragma unroll
        for (int r = 0; r < 4; r++) {
            float ar = vr[r], ai = vi[r];
            float br = __shfl_xor_sync(0xffffffffu, ar, h);
            float bi = __shfl_xor_sync(0xffffffffu, ai, h);
            if (hiLane) {
                float dr = br - ar, di = bi - ai;
                vr[r] = dr * w.x - di * w.y;
                vi[r] = dr * w.y + di * w.x;
            } else {
                vr[r] = ar + br;
                vi[r] = ai + bi;
            }
        }
    }
}

// ---------------------------------------------------------------------------
// K1: one block per IMAGE. Row FFTs stored at NATURAL col index (bitrev of
// slot), cols 0..64 only. Column FFTs on 65 cols; |X|^2 -> g_psd. Also norms.
// smem: re/im at stride 65 (col reads: stride 65 mod 32 = 1 -> conflict-free).
// ---------------------------------------------------------------------------
__global__ __launch_bounds__(512, 2)
void fft_psd_kernel(const float* __restrict__ x1, const float* __restrict__ x2) {
    extern __shared__ float smem[];
    float*  s_re = smem;                   // 128*65
    float*  s_im = smem + 128 * NCOL;      // 128*65
    float2* s_tw = (float2*)(smem + 2 * 128 * NCOL);
    __shared__ float s_red[16];

    int t = threadIdx.x, lane = t & 31, warp = t >> 5;  // 16 warps
    int img = blockIdx.x;
    const float* src = (img < 128) ? x1 + (size_t)img * NPIX
                                   : x2 + (size_t)(img - 128) * NPIX;
    if (t < 64) {
        float sn, cs;
        sincosf(-6.283185307179586f * (float)t / 128.0f, &sn, &cs);
        s_tw[t] = make_float2(cs, sn);
    }
    __syncthreads();

    float nrm = 0.f;
    for (int q = 0; q < 8; q++) {
        int row = q * 16 + warp;
        float vr[4], vi[4];
        #pragma unroll
        for (int r = 0; r < 4; r++) {
            float x = src[row * 128 + r * 32 + lane];
            vr[r] = x; vi[r] = 0.f;
            nrm += x * x;
        }
        fft128(vr, vi, s_tw, lane);
        #pragma unroll
        for (int r = 0; r < 4; r++) {
            int p = r * 32 + lane;
            int k = __brev((unsigned)p) >> 25;  // natural bin
            if (k < NCOL) {
                s_re[row * NCOL + k] = vr[r];
                s_im[row * NCOL + k] = vi[r];
            }
        }
    }

    #pragma unroll
    for (int o = 16; o; o >>= 1) nrm += __shfl_xor_sync(0xffffffffu, nrm, o);
    if (lane == 0) s_red[warp] = nrm;
    __syncthreads();  // also orders row stores before col loads
    if (t == 0) {
        float tot = 0.f;
        for (int w = 0; w < 16; w++) tot += s_red[w];
        g_norm[img] = tot;
    }

    float* psd = g_psd + (size_t)img * NBIN;
    for (int q = 0; q < 5; q++) {
        int col = q * 16 + warp;
        if (col >= NCOL) continue;
        float vr[4], vi[4];
        #pragma unroll
        for (int r = 0; r < 4; r++) {
            vr[r] = s_re[(r * 32 + lane) * NCOL + col];
            vi[r] = s_im[(r * 32 + lane) * NCOL + col];
        }
        fft128(vr, vi, s_tw, lane);
        #pragma unroll
        for (int r = 0; r < 4; r++)
            psd[col * 128 + r * 32 + lane] = vr[r] * vr[r] + vi[r] * vi[r];
    }
}

// ---------------------------------------------------------------------------
// K2: partial Gram, K-chunk of 128 per block (4 sub-stages of 32).
// ---------------------------------------------------------------------------
__global__ __launch_bounds__(256, 2)
void gram_kernel(const float* __restrict__ A, const float* __restrict__ B) {
    __shared__ float aT[32 * 132];
    __shared__ float bT[32 * 132];
    int t = threadIdx.x, kb = blockIdx.x;
    int i0 = (t >> 4) << 3, j0 = (t & 15) << 3;

    float acc[8][8];
    #pragma unroll
    for (int u = 0; u < 8; u++)
        #pragma unroll
        for (int v = 0; v < 8; v++) acc[u][v] = 0.f;

    for (int stg = 0; stg < 4; stg++) {
        int k0 = kb * 128 + stg * 32;
        __syncthreads();
        #pragma unroll
        for (int v = 0; v < 16; v++) {
            int id = t + (v << 8);
            int row = id >> 5, kk = id & 31;
            aT[kk * 132 + row] = A[(size_t)row * NPIX + k0 + kk];
            bT[kk * 132 + row] = B[(size_t)row * NPIX + k0 + kk];
        }
        __syncthreads();
        #pragma unroll 4
        for (int kk = 0; kk < 32; kk++) {
            float4 a0 = *(const float4*)&aT[kk * 132 + i0];
            float4 a1 = *(const float4*)&aT[kk * 132 + i0 + 4];
            float4 b0 = *(const float4*)&bT[kk * 132 + j0];
            float4 b1 = *(const float4*)&bT[kk * 132 + j0 + 4];
            float av[8] = {a0.x, a0.y, a0.z, a0.w, a1.x, a1.y, a1.z, a1.w};
            float bv[8] = {b0.x, b0.y, b0.z, b0.w, b1.x, b1.y, b1.z, b1.w};
            #pragma unroll
            for (int u = 0; u < 8; u++)
                #pragma unroll
                for (int v = 0; v < 8; v++)
                    acc[u][v] = fmaf(av[u], bv[v], acc[u][v]);
        }
    }

    float* out = g_gram_part + (size_t)kb * NPIX;
    #pragma unroll
    for (int u = 0; u < 8; u++) {
        *(float4*)&out[(i0 + u) * 128 + j0] =
            make_float4(acc[u][0], acc[u][1], acc[u][2], acc[u][3]);
        *(float4*)&out[(i0 + u) * 128 + j0 + 4] =
            make_float4(acc[u][4], acc[u][5], acc[u][6], acc[u][7]);
    }
}

// ---------------------------------------------------------------------------
// K3a/K3b: two-stage gram-partial reduction -> Dist.
// ---------------------------------------------------------------------------
__global__ __launch_bounds__(128)
void dist_partial_kernel() {  // grid (128, 8)
    int e = blockIdx.x * 128 + threadIdx.x;
    int y = blockIdx.y;
    float s = 0.f;
    #pragma unroll
    for (int pp = 0; pp < 16; pp++)
        s += g_gram_part[(size_t)(y * 16 + pp) * NPIX + e];
    g_dtmp[(size_t)y * NPIX + e] = s;
}

__global__ __launch_bounds__(128)
void dist_final_kernel() {  // grid 128
    int e = blockIdx.x * 128 + threadIdx.x;
    float s = 0.f;
    #pragma unroll
    for (int y = 0; y < 8; y++) s += g_dtmp[(size_t)y * NPIX + e];
    float d2 = g_norm[blockIdx.x] + g_norm[128 + threadIdx.x] - 2.f * s;
    g_dist[e] = sqrtf(fmaxf(d2, 0.f));
}

// ---------------------------------------------------------------------------
// K4a/K4b: two-stage psd reduction over 256 images -> per-col weighted sums.
// ---------------------------------------------------------------------------
__global__ __launch_bounds__(128)
void psd_partial_kernel() {  // grid (65, 8)
    int e = blockIdx.x * 128 + threadIdx.x;
    int y = blockIdx.y;
    float s = 0.f;
    #pragma unroll 8
    for (int p = 0; p < 32; p++)
        s += g_psd[(size_t)(y * 32 + p) * NBIN + e];
    g_ptmp[(size_t)y * NBIN + e] = s;
}

__global__ __launch_bounds__(128)
void psd_final_kernel() {  // grid 65
    __shared__ float sbuf[8];
    int t = threadIdx.x, lane = t & 31, warp = t >> 5;
    int e = blockIdx.x * 128 + t;
    float s = 0.f;
    #pragma unroll
    for (int y = 0; y < 8; y++) s += g_ptmp[(size_t)y * NBIN + e];
    float avg = s * (1.f / 256.f);
    float w = (blockIdx.x >= 1 && blockIdx.x <= 63) ? 2.f : 1.f;
    float v1 = w * logf(avg), v2 = w * avg;
    #pragma unroll
    for (int o = 16; o; o >>= 1) {
        v1 += __shfl_xor_sync(0xffffffffu, v1, o);
        v2 += __shfl_xor_sync(0xffffffffu, v2, o);
    }
    if (lane == 0) { sbuf[warp] = v1; sbuf[4 + warp] = v2; }
    __syncthreads();
    if (t == 0) {
        g_redL[blockIdx.x] = sbuf[0] + sbuf[1] + sbuf[2] + sbuf[3];
        g_redA[blockIdx.x] = sbuf[4] + sbuf[5] + sbuf[6] + sbuf[7];
    }
}

// ---------------------------------------------------------------------------
// K5: CE over log_softmax rows + psd scalar -> output.
// ---------------------------------------------------------------------------
__global__ __launch_bounds__(1024)
void final_kernel(float* __restrict__ out) {
    __shared__ float sbuf[32];
    int t = threadIdx.x, lane = t & 31, warp = t >> 5;  // 32 warps
    float c = 0.f;
    #pragma unroll
    for (int rr = 0; rr < 4; rr++) {
        int row = warp * 4 + rr;
        const float* rp = g_dist + row * 128;
        float e0 = rp[lane], e1 = rp[lane + 32], e2 = rp[lane + 64], e3 = rp[lane + 96];
        float m = fmaxf(fmaxf(e0, e1), fmaxf(e2, e3));
        #pragma unroll
        for (int o = 16; o; o >>= 1) m = fmaxf(m, __shfl_xor_sync(0xffffffffu, m, o));
        float se = expf(e0 - m) + expf(e1 - m) + expf(e2 - m) + expf(e3 - m);
        #pragma unroll
        for (int o = 16; o; o >>= 1) se += __shfl_xor_sync(0xffffffffu, se, o);
        c += rp[row] - (m + logf(se));
    }
    if (lane == 0) sbuf[warp] = c;
    __syncthreads();
    if (t == 0) {
        float cs = 0.f;
        for (int w = 0; w < 32; w++) cs += sbuf[w];
        float ce = -cs / 128.f;
        float lsum = 0.f, asum = 0.f;
        for (int k = 0; k < NCOL; k++) { lsum += g_redL[k]; asum += g_redA[k]; }
        float r = lsum / 16384.f - logf(asum / 16384.f);
        out[0] = ce - 0.1f * r;
    }
}

// ---------------------------------------------------------------------------
extern "C" void kernel_launch(void* const* d_in, const int* in_sizes, int n_in,
                              void* d_out, int out_size) {
    const float* x1 = (const float*)d_in[0];
    const float* x2 = (const float*)d_in[1];
    float* out = (float*)d_out;

    static cudaStream_t s1 = 0;
    static cudaEvent_t ev_fork, ev_fft, ev_join;
    static bool inited = false;
    if (!inited) {
        cudaStreamCreateWithFlags(&s1, cudaStreamNonBlocking);
        cudaEventCreateWithFlags(&ev_fork, cudaEventDisableTiming);
        cudaEventCreateWithFlags(&ev_fft, cudaEventDisableTiming);
        cudaEventCreateWithFlags(&ev_join, cudaEventDisableTiming);
        const int SMEM_FFT = (2 * 128 * NCOL) * 4 + 64 * 8;  // 66,816 B
        cudaFuncSetAttribute(fft_psd_kernel,
                             cudaFuncAttributeMaxDynamicSharedMemorySize, SMEM_FFT);
        inited = true;
    }
    const int SMEM_FFT = (2 * 128 * NCOL) * 4 + 64 * 8;

    // fork: gram chain on s1
    cudaEventRecord(ev_fork, 0);
    cudaStreamWaitEvent(s1, ev_fork, 0);

    // FFT chain (legacy stream)
    fft_psd_kernel<<<256, 512, SMEM_FFT>>>(x1, x2);
    cudaEventRecord(ev_fft, 0);  // norms + psd ready after this
    psd_partial_kernel<<<dim3(65, 8), 128>>>();
    psd_final_kernel<<<65, 128>>>();

    // Gram chain (s1)
    gram_kernel<<<NB_GRAM, 256, 0, s1>>>(x1, x2);
    dist_partial_kernel<<<dim3(128, 8), 128, 0, s1>>>();
    cudaStreamWaitEvent(s1, ev_fft, 0);  // dist_final needs g_norm
    dist_final_kernel<<<128, 128, 0, s1>>>();
    cudaEventRecord(ev_join, s1);

    // join + final
    cudaStreamWaitEvent(0, ev_join, 0);
    final_kernel<<<1, 1024>>>(out);
}

// round 3
// speedup vs baseline: 1.6944x; 1.0922x over previous
#include <cuda_runtime.h>
#include <cuda_bf16.h>
#include <math.h>
#include <stdint.h>

// OneClassLoss on GB300 — R3.
//  legacy: fftc (complex-packed pair FFT) -> psd_partial -> psd_final
//  s1:     conv (fp32 -> bf16 hi/lo) -> gram_mma (96 blocks, HMMA) ->
//          dist_partial -> [wait fft: norms] -> dist_final
//  join:   final (CE + psd scalar)

#define NPIX 16384

__device__ __nv_bfloat16 g_Ahi[128 * NPIX], g_Alo[128 * NPIX];
__device__ __nv_bfloat16 g_Bhi[128 * NPIX], g_Blo[128 * NPIX];
__device__ float g_psd[128 * NPIX];       // per-pair |Z|^2, slot layout c*128+p
__device__ float g_ptmp[8 * NPIX];
__device__ float g_gram_part[96 * NPIX];  // bf16-split partial Gram
__device__ float g_dtmp[8 * NPIX];
__device__ float g_norm[256];
__device__ float g_dist[NPIX];
__device__ float g_redL[128], g_redA[128];

// ---------------------------------------------------------------------------
// 128-pt DIF radix-2 complex FFT, one warp, 4 values/lane (n = r*32+lane).
// Output slot p holds bin rev7(p).
// ---------------------------------------------------------------------------
__device__ __forceinline__ void fft128(float vr[4], float vi[4],
                                       const float2* __restrict__ tw, int lane) {
    #pragma unroll
    for (int r = 0; r < 2; r++) {  // h=64
        float2 w = tw[r * 32 + lane];
        float ur = vr[r], ui = vi[r], xr = vr[r + 2], xi = vi[r + 2];
        vr[r] = ur + xr; vi[r] = ui + xi;
        float dr = ur - xr, di = ui - xi;
        vr[r + 2] = dr * w.x - di * w.y;
        vi[r + 2] = dr * w.y + di * w.x;
    }
    {  // h=32
        float2 w = tw[2 * lane];
        #pragma unroll
        for (int half = 0; half < 2; half++) {
            int r = half * 2;
            float ur = vr[r], ui = vi[r], xr = vr[r + 1], xi = vi[r + 1];
            vr[r] = ur + xr; vi[r] = ui + xi;
            float dr = ur - xr, di = ui - xi;
            vr[r + 1] = dr * w.x - di * w.y;
            vi[r + 1] = dr * w.y + di * w.x;
        }
    }
    #pragma unroll
    for (int st = 0; st < 5; st++) {  // h = 16,8,4,2,1
        const int h = 16 >> st;
        const int k = (lane & (h - 1)) * (64 / h);
        float2 w = tw[k];
        bool hiLane = (lane & h) != 0;
        #pragma unroll
        for (int r = 0; r < 4; r++) {
            float ar = vr[r], ai = vi[r];
            float br = __shfl_xor_sync(0xffffffffu, ar, h);
            float bi = __shfl_xor_sync(0xffffffffu, ai, h);
            if (hiLane) {
                float dr = br - ar, di = bi - ai;
                vr[r] = dr * w.x - di * w.y;
                vi[r] = dr * w.y + di * w.x;
            } else {
                vr[r] = ar + br;
                vi[r] = ai + bi;
            }
        }
    }
}

// ---------------------------------------------------------------------------
// K1: one block per pair b. z = x1[b] + i*x2[b]; 2D complex FFT; store |Z|^2.
// Also norms: ||x1||^2 = sum re^2, ||x2||^2 = sum im^2.
// ---------------------------------------------------------------------------
__global__ __launch_bounds__(512, 1)
void fftc_kernel(const float* __restrict__ x1, const float* __restrict__ x2) {
    extern __shared__ float smem[];
    float*  s_re = smem;                     // 128*129
    float*  s_im = smem + 128 * 129;
    float2* s_tw = (float2*)(smem + 2 * 128 * 129);
    __shared__ float s_red[32];

    int t = threadIdx.x, lane = t & 31, warp = t >> 5;  // 16 warps
    int b = blockIdx.x;
    const float* p1 = x1 + (size_t)b * NPIX;
    const float* p2 = x2 + (size_t)b * NPIX;

    if (t < 64) {
        float sn, cs;
        sincosf(-6.283185307179586f * (float)t / 128.0f, &sn, &cs);
        s_tw[t] = make_float2(cs, sn);
    }
    __syncthreads();

    float n1 = 0.f, n2 = 0.f;
    for (int q = 0; q < 8; q++) {
        int row = q * 16 + warp;
        float vr[4], vi[4];
        #pragma unroll
        for (int r = 0; r < 4; r++) {
            float xr = p1[row * 128 + r * 32 + lane];
            float xi = p2[row * 128 + r * 32 + lane];
            vr[r] = xr; vi[r] = xi;
            n1 += xr * xr; n2 += xi * xi;
        }
        fft128(vr, vi, s_tw, lane);
        #pragma unroll
        for (int r = 0; r < 4; r++) {
            int p = r * 32 + lane;
            int k = __brev((unsigned)p) >> 25;  // natural col bin
            s_re[row * 129 + k] = vr[r];
            s_im[row * 129 + k] = vi[r];
        }
    }

    #pragma unroll
    for (int o = 16; o; o >>= 1) {
        n1 += __shfl_xor_sync(0xffffffffu, n1, o);
        n2 += __shfl_xor_sync(0xffffffffu, n2, o);
    }
    if (lane == 0) { s_red[warp] = n1; s_red[16 + warp] = n2; }
    __syncthreads();  // also orders row stores before col loads
    if (t == 0) {
        float a = 0.f, c = 0.f;
        for (int w = 0; w < 16; w++) { a += s_red[w]; c += s_red[16 + w]; }
        g_norm[b] = a; g_norm[128 + b] = c;
    }

    float* psd = g_psd + (size_t)b * NPIX;
    for (int q = 0; q < 8; q++) {
        int col = q * 16 + warp;
        float vr[4], vi[4];
        #pragma unroll
        for (int r = 0; r < 4; r++) {
            vr[r] = s_re[(r * 32 + lane) * 129 + col];
            vi[r] = s_im[(r * 32 + lane) * 129 + col];
        }
        fft128(vr, vi, s_tw, lane);
        #pragma unroll
        for (int r = 0; r < 4; r++)
            psd[col * 128 + r * 32 + lane] = vr[r] * vr[r] + vi[r] * vi[r];
    }
}

// ---------------------------------------------------------------------------
// conv: fp32 -> (hi, lo) bf16 split.  grid (2048, 2) x 256.
// ---------------------------------------------------------------------------
__global__ __launch_bounds__(256)
void conv_kernel(const float* __restrict__ x1, const float* __restrict__ x2) {
    int i4 = blockIdx.x * 256 + threadIdx.x;
    const float4* src = (const float4*)(blockIdx.y ? x2 : x1);
    __nv_bfloat162* hi = (__nv_bfloat162*)(blockIdx.y ? g_Bhi : g_Ahi);
    __nv_bfloat162* lo = (__nv_bfloat162*)(blockIdx.y ? g_Blo : g_Alo);
    float4 v = src[i4];
    __nv_bfloat16 hx = __float2bfloat16_rn(v.x), hy = __float2bfloat16_rn(v.y);
    __nv_bfloat16 hz = __float2bfloat16_rn(v.z), hw = __float2bfloat16_rn(v.w);
    __nv_bfloat16 lx = __float2bfloat16_rn(v.x - __bfloat162float(hx));
    __nv_bfloat16 ly = __float2bfloat16_rn(v.y - __bfloat162float(hy));
    __nv_bfloat16 lz = __float2bfloat16_rn(v.z - __bfloat162float(hz));
    __nv_bfloat16 lw = __float2bfloat16_rn(v.w - __bfloat162float(hw));
    hi[i4 * 2]     = __nv_bfloat162(hx, hy);
    hi[i4 * 2 + 1] = __nv_bfloat162(hz, hw);
    lo[i4 * 2]     = __nv_bfloat162(lx, ly);
    lo[i4 * 2 + 1] = __nv_bfloat162(lz, lw);
}

// ---------------------------------------------------------------------------
// gram_mma: 96 blocks = 3 terms x 32 K-chunks (K=512 each, 4 stages of 128).
// Block: 256 threads (8 warps), warp ws owns rows ws*16..+15 (full N=128).
// smem: A,B tiles 128 x 128 bf16, row stride 136 bf16 (272 B, conflict-free
// ldmatrix). Partial 128x128 fp32 -> g_gram_part[bid].
// ---------------------------------------------------------------------------
__device__ __forceinline__ void ldsm4(uint32_t& r0, uint32_t& r1,
                                      uint32_t& r2, uint32_t& r3, uint32_t a) {
    asm volatile("ldmatrix.sync.aligned.m8n8.x4.shared.b16 {%0,%1,%2,%3}, [%4];"
                 : "=r"(r0), "=r"(r1), "=r"(r2), "=r"(r3) : "r"(a));
}
__device__ __forceinline__ void mma16816(float d[4], const uint32_t a[4],
                                         uint32_t b0, uint32_t b1) {
    asm volatile(
        "mma.sync.aligned.m16n8k16.row.col.f32.bf16.bf16.f32 "
        "{%0,%1,%2,%3}, {%4,%5,%6,%7}, {%8,%9}, {%0,%1,%2,%3};"
        : "+f"(d[0]), "+f"(d[1]), "+f"(d[2]), "+f"(d[3])
        : "r"(a[0]), "r"(a[1]), "r"(a[2]), "r"(a[3]), "r"(b0), "r"(b1));
}

#define SROW 272  // smem row stride bytes (136 bf16)

__global__ __launch_bounds__(256, 2)
void gram_mma_kernel() {
    extern __shared__ char gsm[];
    char* smA = gsm;                 // 128*272 = 34816 B
    char* smB = gsm + 128 * SROW;    // 34816 B
    uint32_t uA = (uint32_t)__cvta_generic_to_shared(smA);
    uint32_t uB = (uint32_t)__cvta_generic_to_shared(smB);

    int t = threadIdx.x, lane = t & 31, ws = t >> 5;
    int bid = blockIdx.x;
    int term = bid >> 5, chunk = bid & 31;
    int k0 = chunk * 512;

    const __nv_bfloat16* gA = (term == 2) ? g_Alo : g_Ahi;
    const __nv_bfloat16* gB = (term == 1) ? g_Blo : g_Bhi;

    float acc[16][4];
    #pragma unroll
    for (int i = 0; i < 16; i++)
        #pragma unroll
        for (int j = 0; j < 4; j++) acc[i][j] = 0.f;

    // ldmatrix lane address bases
    uint32_t aBase = uA + (ws * 16 + (lane & 15)) * SROW + (lane >> 4) * 16;
    uint32_t bBase = uB + ((lane & 7) + ((lane >> 4) << 3)) * SROW + ((lane & 8) << 1);

    for (int st = 0; st < 4; st++) {
        int ks = k0 + st * 128;
        __syncthreads();
        #pragma unroll
        for (int c = 0; c < 8; c++) {
            int id = t + c * 256;        // 2048 16B-chunks
            int row = id >> 4, o = id & 15;
            *(uint4*)(smA + row * SROW + o * 16) =
                *(const uint4*)(gA + (size_t)row * NPIX + ks + o * 8);
            *(uint4*)(smB + row * SROW + o * 16) =
                *(const uint4*)(gB + (size_t)row * NPIX + ks + o * 8);
        }
        __syncthreads();
        #pragma unroll
        for (int kk = 0; kk < 8; kk++) {
            uint32_t a[4];
            ldsm4(a[0], a[1], a[2], a[3], aBase + kk * 32);
            #pragma unroll
            for (int j = 0; j < 8; j++) {
                uint32_t b0, b1, b2, b3;
                ldsm4(b0, b1, b2, b3, bBase + j * 16 * SROW + kk * 32);
                mma16816(acc[2 * j],     a, b0, b1);
                mma16816(acc[2 * j + 1], a, b2, b3);
            }
        }
    }

    float* out = g_gram_part + (size_t)bid * NPIX;
    int g = lane >> 2, tt = lane & 3;
    #pragma unroll
    for (int i = 0; i < 16; i++) {
        int col = i * 8 + tt * 2;
        int r0 = ws * 16 + g;
        *(float2*)&out[r0 * 128 + col]       = make_float2(acc[i][0], acc[i][1]);
        *(float2*)&out[(r0 + 8) * 128 + col] = make_float2(acc[i][2], acc[i][3]);
    }
}

// ---------------------------------------------------------------------------
// dist reduce: 96 partials, two stages.
// ---------------------------------------------------------------------------
__global__ __launch_bounds__(128)
void dist_partial_kernel() {  // grid (128, 8)
    int e = blockIdx.x * 128 + threadIdx.x;
    int y = blockIdx.y;
    float s = 0.f;
    #pragma unroll
    for (int pp = 0; pp < 12; pp++)
        s += g_gram_part[(size_t)(y * 12 + pp) * NPIX + e];
    g_dtmp[(size_t)y * NPIX + e] = s;
}

__global__ __launch_bounds__(128)
void dist_final_kernel() {  // grid 128
    int e = blockIdx.x * 128 + threadIdx.x;
    float s = 0.f;
    #pragma unroll
    for (int y = 0; y < 8; y++) s += g_dtmp[(size_t)y * NPIX + e];
    float d2 = g_norm[blockIdx.x] + g_norm[128 + threadIdx.x] - 2.f * s;
    g_dist[e] = sqrtf(fmaxf(d2, 0.f));
}

// ---------------------------------------------------------------------------
// psd reduce over 128 pairs, then Hermitian-pair recombination:
// avgpsd[bin(i)] = (T[i] + T[partner(i)]) / (2*256).
// ---------------------------------------------------------------------------
__global__ __launch_bounds__(128)
void psd_partial_kernel() {  // grid (128, 8)
    int e = blockIdx.x * 128 + threadIdx.x;
    int y = blockIdx.y;
    float s = 0.f;
    #pragma unroll
    for (int p = 0; p < 16; p++)
        s += g_psd[(size_t)(y * 16 + p) * NPIX + e];
    g_ptmp[(size_t)y * NPIX + e] = s;
}

__global__ __launch_bounds__(128)
void psd_final_kernel() {  // grid 128 (one block per natural col)
    __shared__ float sbuf[8];
    int t = threadIdx.x, lane = t & 31, warp = t >> 5;
    int col = blockIdx.x, p = t;
    int i = col * 128 + p;
    int kr = __brev((unsigned)p) >> 25;            // natural row bin
    int pp = __brev((unsigned)((128 - kr) & 127)) >> 25;
    int ip = ((128 - col) & 127) * 128 + pp;       // slot of bin (-kr, -col)
    float Ti = 0.f, Tp = 0.f;
    #pragma unroll
    for (int y = 0; y < 8; y++) {
        Ti += g_ptmp[(size_t)y * NPIX + i];
        Tp += g_ptmp[(size_t)y * NPIX + ip];
    }
    float avg = (Ti + Tp) * (0.5f / 256.f);
    float v1 = logf(avg), v2 = avg;
    #pragma unroll
    for (int o = 16; o; o >>= 1) {
        v1 += __shfl_xor_sync(0xffffffffu, v1, o);
        v2 += __shfl_xor_sync(0xffffffffu, v2, o);
    }
    if (lane == 0) { sbuf[warp] = v1; sbuf[4 + warp] = v2; }
    __syncthreads();
    if (t == 0) {
        g_redL[col] = sbuf[0] + sbuf[1] + sbuf[2] + sbuf[3];
        g_redA[col] = sbuf[4] + sbuf[5] + sbuf[6] + sbuf[7];
    }
}

// ---------------------------------------------------------------------------
// K5: CE + psd scalar.
// ---------------------------------------------------------------------------
__global__ __launch_bounds__(1024)
void final_kernel(float* __restrict__ out) {
    __shared__ float sbuf[32];
    int t = threadIdx.x, lane = t & 31, warp = t >> 5;
    float c = 0.f;
    #pragma unroll
    for (int rr = 0; rr < 4; rr++) {
        int row = warp * 4 + rr;
        const float* rp = g_dist + row * 128;
        float e0 = rp[lane], e1 = rp[lane + 32], e2 = rp[lane + 64], e3 = rp[lane + 96];
        float m = fmaxf(fmaxf(e0, e1), fmaxf(e2, e3));
        #pragma unroll
        for (int o = 16; o; o >>= 1) m = fmaxf(m, __shfl_xor_sync(0xffffffffu, m, o));
        float se = expf(e0 - m) + expf(e1 - m) + expf(e2 - m) + expf(e3 - m);
        #pragma unroll
        for (int o = 16; o; o >>= 1) se += __shfl_xor_sync(0xffffffffu, se, o);
        c += rp[row] - (m + logf(se));
    }
    if (lane == 0) sbuf[warp] = c;
    __syncthreads();
    if (t == 0) {
        float cs = 0.f;
        for (int w = 0; w < 32; w++) cs += sbuf[w];
        float ce = -cs / 128.f;
        float lsum = 0.f, asum = 0.f;
        for (int k = 0; k < 128; k++) { lsum += g_redL[k]; asum += g_redA[k]; }
        float r = lsum / 16384.f - logf(asum / 16384.f);
        out[0] = ce - 0.1f * r;
    }
}

// ---------------------------------------------------------------------------
extern "C" void kernel_launch(void* const* d_in, const int* in_sizes, int n_in,
                              void* d_out, int out_size) {
    const float* x1 = (const float*)d_in[0];
    const float* x2 = (const float*)d_in[1];
    float* out = (float*)d_out;

    const int SMEM_FFT = (2 * 128 * 129) * 4 + 64 * 8;  // 132,608 B
    const int SMEM_GRAM = 2 * 128 * SROW;               // 69,632 B

    static cudaStream_t s1 = 0;
    static cudaEvent_t ev_fork, ev_fft, ev_join;
    static bool inited = false;
    if (!inited) {
        cudaStreamCreateWithFlags(&s1, cudaStreamNonBlocking);
        cudaEventCreateWithFlags(&ev_fork, cudaEventDisableTiming);
        cudaEventCreateWithFlags(&ev_fft, cudaEventDisableTiming);
        cudaEventCreateWithFlags(&ev_join, cudaEventDisableTiming);
        cudaFuncSetAttribute(fftc_kernel,
                             cudaFuncAttributeMaxDynamicSharedMemorySize, SMEM_FFT);
        cudaFuncSetAttribute(gram_mma_kernel,
                             cudaFuncAttributeMaxDynamicSharedMemorySize, SMEM_GRAM);
        inited = true;
    }

    cudaEventRecord(ev_fork, 0);
    cudaStreamWaitEvent(s1, ev_fork, 0);

    // FFT / psd chain (legacy)
    fftc_kernel<<<128, 512, SMEM_FFT>>>(x1, x2);
    cudaEventRecord(ev_fft, 0);  // g_norm + g_psd ready
    psd_partial_kernel<<<dim3(128, 8), 128>>>();
    psd_final_kernel<<<128, 128>>>();

    // Gram chain (s1)
    conv_kernel<<<dim3(2048, 2), 256, 0, s1>>>(x1, x2);
    gram_mma_kernel<<<96, 256, SMEM_GRAM, s1>>>();
    dist_partial_kernel<<<dim3(128, 8), 128, 0, s1>>>();
    cudaStreamWaitEvent(s1, ev_fft, 0);  // needs g_norm
    dist_final_kernel<<<128, 128, 0, s1>>>();
    cudaEventRecord(ev_join, s1);

    cudaStreamWaitEvent(0, ev_join, 0);
    final_kernel<<<1, 1024>>>(out);
}

// round 4
// speedup vs baseline: 2.2192x; 1.3098x over previous
#include <cuda_runtime.h>
#include <cuda_bf16.h>
#include <math.h>
#include <stdint.h>

// OneClassLoss on GB300 — R4.
//  legacy: fft_row (512 blk, transpose->g_spec, norms) -> fft_col (512 blk,
//          psd) -> psd_partial -> psd_final
//  s1:     gram_fused (128 blk: fp32 load + bf16 hi/lo split in-smem, 3-term
//          single-accumulator HMMA) -> dist_partial -> [ev_row] dist_final
//  join:   final (CE + psd scalar)

#define NPIX 16384

__device__ float2 g_spec[128 * NPIX];      // row-FFT output, [pair][col][row] (16 MB)
__device__ float  g_psd[128 * NPIX];       // per-pair |Z|^2, [pair][col*128+slot]
__device__ float  g_ptmp[8 * NPIX];
__device__ float  g_gram_part[128 * NPIX]; // partial Gram per K-chunk (8 MB)
__device__ float  g_dtmp[8 * NPIX];
__device__ float  g_np1[512], g_np2[512];  // norm partials (4 per image)
__device__ float  g_dist[NPIX];
__device__ float  g_redL[128], g_redA[128];

// ---------------------------------------------------------------------------
// 128-pt DIF radix-2 complex FFT, one warp, 4 values/lane (n = r*32+lane).
// Output slot p holds bin rev7(p).
// ---------------------------------------------------------------------------
__device__ __forceinline__ void fft128(float vr[4], float vi[4],
                                       const float2* __restrict__ tw, int lane) {
    #pragma unroll
    for (int r = 0; r < 2; r++) {  // h=64
        float2 w = tw[r * 32 + lane];
        float ur = vr[r], ui = vi[r], xr = vr[r + 2], xi = vi[r + 2];
        vr[r] = ur + xr; vi[r] = ui + xi;
        float dr = ur - xr, di = ui - xi;
        vr[r + 2] = dr * w.x - di * w.y;
        vi[r + 2] = dr * w.y + di * w.x;
    }
    {  // h=32
        float2 w = tw[2 * lane];
        #pragma unroll
        for (int half = 0; half < 2; half++) {
            int r = half * 2;
            float ur = vr[r], ui = vi[r], xr = vr[r + 1], xi = vi[r + 1];
            vr[r] = ur + xr; vi[r] = ui + xi;
            float dr = ur - xr, di = ui - xi;
            vr[r + 1] = dr * w.x - di * w.y;
            vi[r + 1] = dr * w.y + di * w.x;
        }
    }
    #pragma unroll
    for (int st = 0; st < 5; st++) {  // h = 16,8,4,2,1
        const int h = 16 >> st;
        const int k = (lane & (h - 1)) * (64 / h);
        float2 w = tw[k];
        bool hiLane = (lane & h) != 0;
        #pragma unroll
        for (int r = 0; r < 4; r++) {
            float ar = vr[r], ai = vi[r];
            float br = __shfl_xor_sync(0xffffffffu, ar, h);
            float bi = __shfl_xor_sync(0xffffffffu, ai, h);
            if (hiLane) {
                float dr = br - ar, di = bi - ai;
                vr[r] = dr * w.x - di * w.y;
                vi[r] = dr * w.y + di * w.x;
            } else {
                vr[r] = ar + br;
                vi[r] = ai + bi;
            }
        }
    }
}

__device__ __forceinline__ void init_tw(float2* s_tw, int t) {
    if (t < 64) {
        float sn, cs;
        sincosf(-6.283185307179586f * (float)t / 128.0f, &sn, &cs);
        s_tw[t] = make_float2(cs, sn);
    }
}

// ---------------------------------------------------------------------------
// fft_row: grid 512 = 128 pairs x 4 row-groups of 32. z = x1 + i*x2.
// De-bitrev into smem transpose buffer, write g_spec[pair][col][rows].
// Also per-block norm partials.
// ---------------------------------------------------------------------------
__global__ __launch_bounds__(256)
void fft_row_kernel(const float* __restrict__ x1, const float* __restrict__ x2) {
    __shared__ float s_re[128 * 33], s_im[128 * 33];
    __shared__ float2 s_tw[64];
    __shared__ float s_red[16];

    int t = threadIdx.x, lane = t & 31, warp = t >> 5;  // 8 warps
    int b = blockIdx.x >> 2, rg = blockIdx.x & 3;
    const float* p1 = x1 + (size_t)b * NPIX;
    const float* p2 = x2 + (size_t)b * NPIX;

    init_tw(s_tw, t);
    __syncthreads();

    float n1 = 0.f, n2 = 0.f;
    #pragma unroll
    for (int q = 0; q < 4; q++) {
        int rl = warp * 4 + q;          // local row 0..31
        int row = rg * 32 + rl;
        float vr[4], vi[4];
        #pragma unroll
        for (int r = 0; r < 4; r++) {
            float xr = p1[row * 128 + r * 32 + lane];
            float xi = p2[row * 128 + r * 32 + lane];
            vr[r] = xr; vi[r] = xi;
            n1 += xr * xr; n2 += xi * xi;
        }
        fft128(vr, vi, s_tw, lane);
        #pragma unroll
        for (int r = 0; r < 4; r++) {
            int p = r * 32 + lane;
            int k = __brev((unsigned)p) >> 25;  // natural col bin
            s_re[k * 33 + rl] = vr[r];
            s_im[k * 33 + rl] = vi[r];
        }
    }

    #pragma unroll
    for (int o = 16; o; o >>= 1) {
        n1 += __shfl_xor_sync(0xffffffffu, n1, o);
        n2 += __shfl_xor_sync(0xffffffffu, n2, o);
    }
    if (lane == 0) { s_red[warp] = n1; s_red[8 + warp] = n2; }
    __syncthreads();  // also orders smem transpose stores before reads
    if (t == 0) {
        float a = 0.f, c = 0.f;
        #pragma unroll
        for (int w = 0; w < 8; w++) { a += s_red[w]; c += s_red[8 + w]; }
        g_np1[blockIdx.x] = a; g_np2[blockIdx.x] = c;
    }

    float2* spec = g_spec + (size_t)b * NPIX;
    #pragma unroll
    for (int it = 0; it < 16; it++) {
        int c = warp + it * 8;  // warp writes one col: 32 rows contiguous
        spec[c * 128 + rg * 32 + lane] =
            make_float2(s_re[c * 33 + lane], s_im[c * 33 + lane]);
    }
}

// ---------------------------------------------------------------------------
// fft_col: grid 512 = 128 pairs x 4 col-groups of 32. Coalesced column loads,
// FFT, |Z|^2 -> g_psd[pair][col*128 + slot].
// ---------------------------------------------------------------------------
__global__ __launch_bounds__(256)
void fft_col_kernel() {
    __shared__ float2 s_tw[64];
    int t = threadIdx.x, lane = t & 31, warp = t >> 5;
    int b = blockIdx.x >> 2, cg = blockIdx.x & 3;
    init_tw(s_tw, t);
    __syncthreads();

    const float2* spec = g_spec + (size_t)b * NPIX;
    float* psd = g_psd + (size_t)b * NPIX;

    #pragma unroll
    for (int q = 0; q < 4; q++) {
        int c = cg * 32 + warp * 4 + q;
        float vr[4], vi[4];
        #pragma unroll
        for (int r = 0; r < 4; r++) {
            float2 z = spec[c * 128 + r * 32 + lane];
            vr[r] = z.x; vi[r] = z.y;
        }
        fft128(vr, vi, s_tw, lane);
        #pragma unroll
        for (int r = 0; r < 4; r++)
            psd[c * 128 + r * 32 + lane] = vr[r] * vr[r] + vi[r] * vi[r];
    }
}

// ---------------------------------------------------------------------------
// gram_fused: 128 blocks, K-chunk 128 (2 stages of 64). Loads fp32, splits to
// bf16 hi/lo in smem, accumulates Ahi*Bhi + Ahi*Blo + Alo*Bhi via HMMA.
// ---------------------------------------------------------------------------
__device__ __forceinline__ void ldsm4(uint32_t& r0, uint32_t& r1,
                                      uint32_t& r2, uint32_t& r3, uint32_t a) {
    asm volatile("ldmatrix.sync.aligned.m8n8.x4.shared.b16 {%0,%1,%2,%3}, [%4];"
                 : "=r"(r0), "=r"(r1), "=r"(r2), "=r"(r3) : "r"(a));
}
__device__ __forceinline__ void mma16816(float d[4], const uint32_t a[4],
                                         uint32_t b0, uint32_t b1) {
    asm volatile(
        "mma.sync.aligned.m16n8k16.row.col.f32.bf16.bf16.f32 "
        "{%0,%1,%2,%3}, {%4,%5,%6,%7}, {%8,%9}, {%0,%1,%2,%3};"
        : "+f"(d[0]), "+f"(d[1]), "+f"(d[2]), "+f"(d[3])
        : "r"(a[0]), "r"(a[1]), "r"(a[2]), "r"(a[3]), "r"(b0), "r"(b1));
}

#define SR 144  // smem row stride bytes for 64-bf16 (128 B) rows

__global__ __launch_bounds__(256, 2)
void gram_fused_kernel(const float* __restrict__ x1, const float* __restrict__ x2) {
    extern __shared__ char gsm[];
    char* sAhi = gsm;
    char* sAlo = gsm + 128 * SR;
    char* sBhi = gsm + 2 * 128 * SR;
    char* sBlo = gsm + 3 * 128 * SR;
    uint32_t uAhi = (uint32_t)__cvta_generic_to_shared(sAhi);
    uint32_t uAlo = (uint32_t)__cvta_generic_to_shared(sAlo);
    uint32_t uBhi = (uint32_t)__cvta_generic_to_shared(sBhi);
    uint32_t uBlo = (uint32_t)__cvta_generic_to_shared(sBlo);

    int t = threadIdx.x, lane = t & 31, ws = t >> 5;
    int k0 = blockIdx.x * 128;

    float acc[16][4];
    #pragma unroll
    for (int i = 0; i < 16; i++)
        #pragma unroll
        for (int j = 0; j < 4; j++) acc[i][j] = 0.f;

    uint32_t aOff = (ws * 16 + (lane & 15)) * SR + (lane >> 4) * 16;
    uint32_t bOff = ((lane & 7) + ((lane >> 4) << 3)) * SR + ((lane & 8) << 1);

    for (int stg = 0; stg < 2; stg++) {
        int ks = k0 + stg * 64;
        __syncthreads();
        // load + split: 128 rows x 64 cols x {A,B}; 8 float4 per thread each
        #pragma unroll
        for (int c = 0; c < 8; c++) {
            int id = t + c * 256;          // 2048 float4 slots
            int row = id >> 4, o = id & 15;
            float4 va = *(const float4*)(x1 + (size_t)row * NPIX + ks + o * 4);
            float4 vb = *(const float4*)(x2 + (size_t)row * NPIX + ks + o * 4);
            __nv_bfloat16 h0 = __float2bfloat16_rn(va.x), h1 = __float2bfloat16_rn(va.y);
            __nv_bfloat16 h2 = __float2bfloat16_rn(va.z), h3 = __float2bfloat16_rn(va.w);
            __nv_bfloat162 ahi0(h0, h1), ahi1(h2, h3);
            __nv_bfloat162 alo0(__float2bfloat16_rn(va.x - __bfloat162float(h0)),
                                __float2bfloat16_rn(va.y - __bfloat162float(h1)));
            __nv_bfloat162 alo1(__float2bfloat16_rn(va.z - __bfloat162float(h2)),
                                __float2bfloat16_rn(va.w - __bfloat162float(h3)));
            *(uint2*)(sAhi + row * SR + o * 8) = *(uint2*)&ahi0;  // ahi0,ahi1 contiguous
            ((uint32_t*)(sAhi + row * SR + o * 8))[1] = *(uint32_t*)&ahi1;
            ((uint32_t*)(sAhi + row * SR + o * 8))[0] = *(uint32_t*)&ahi0;
            ((uint32_t*)(sAlo + row * SR + o * 8))[0] = *(uint32_t*)&alo0;
            ((uint32_t*)(sAlo + row * SR + o * 8))[1] = *(uint32_t*)&alo1;
            __nv_bfloat16 g0 = __float2bfloat16_rn(vb.x), g1 = __float2bfloat16_rn(vb.y);
            __nv_bfloat16 g2 = __float2bfloat16_rn(vb.z), g3 = __float2bfloat16_rn(vb.w);
            __nv_bfloat162 bhi0(g0, g1), bhi1(g2, g3);
            __nv_bfloat162 blo0(__float2bfloat16_rn(vb.x - __bfloat162float(g0)),
                                __float2bfloat16_rn(vb.y - __bfloat162float(g1)));
            __nv_bfloat162 blo1(__float2bfloat16_rn(vb.z - __bfloat162float(g2)),
                                __float2bfloat16_rn(vb.w - __bfloat162float(g3)));
            ((uint32_t*)(sBhi + row * SR + o * 8))[0] = *(uint32_t*)&bhi0;
            ((uint32_t*)(sBhi + row * SR + o * 8))[1] = *(uint32_t*)&bhi1;
            ((uint32_t*)(sBlo + row * SR + o * 8))[0] = *(uint32_t*)&blo0;
            ((uint32_t*)(sBlo + row * SR + o * 8))[1] = *(uint32_t*)&blo1;
        }
        __syncthreads();
        #pragma unroll
        for (int kk = 0; kk < 4; kk++) {
            uint32_t ah[4], al[4];
            ldsm4(ah[0], ah[1], ah[2], ah[3], uAhi + aOff + kk * 32);
            ldsm4(al[0], al[1], al[2], al[3], uAlo + aOff + kk * 32);
            #pragma unroll
            for (int j = 0; j < 8; j++) {
                uint32_t h0, h1, h2, h3, l0, l1, l2, l3;
                ldsm4(h0, h1, h2, h3, uBhi + bOff + j * 16 * SR + kk * 32);
                ldsm4(l0, l1, l2, l3, uBlo + bOff + j * 16 * SR + kk * 32);
                mma16816(acc[2 * j],     ah, h0, h1);
                mma16816(acc[2 * j + 1], ah, h2, h3);
                mma16816(acc[2 * j],     ah, l0, l1);
                mma16816(acc[2 * j + 1], ah, l2, l3);
                mma16816(acc[2 * j],     al, h0, h1);
                mma16816(acc[2 * j + 1], al, h2, h3);
            }
        }
    }

    float* out = g_gram_part + (size_t)blockIdx.x * NPIX;
    int g = lane >> 2, tt = lane & 3;
    #pragma unroll
    for (int i = 0; i < 16; i++) {
        int col = i * 8 + tt * 2;
        int r0 = ws * 16 + g;
        *(float2*)&out[r0 * 128 + col]       = make_float2(acc[i][0], acc[i][1]);
        *(float2*)&out[(r0 + 8) * 128 + col] = make_float2(acc[i][2], acc[i][3]);
    }
}

// ---------------------------------------------------------------------------
// reductions
// ---------------------------------------------------------------------------
__global__ __launch_bounds__(128)
void dist_partial_kernel() {  // grid (128, 8)
    int e = blockIdx.x * 128 + threadIdx.x;
    int y = blockIdx.y;
    float s = 0.f;
    #pragma unroll
    for (int pp = 0; pp < 16; pp++)
        s += g_gram_part[(size_t)(y * 16 + pp) * NPIX + e];
    g_dtmp[(size_t)y * NPIX + e] = s;
}

__global__ __launch_bounds__(128)
void dist_final_kernel() {  // grid 128
    int bi = blockIdx.x, t = threadIdx.x;
    int e = bi * 128 + t;
    float s = 0.f;
    #pragma unroll
    for (int y = 0; y < 8; y++) s += g_dtmp[(size_t)y * NPIX + e];
    float n1 = g_np1[bi * 4] + g_np1[bi * 4 + 1] + g_np1[bi * 4 + 2] + g_np1[bi * 4 + 3];
    float n2 = g_np2[t * 4] + g_np2[t * 4 + 1] + g_np2[t * 4 + 2] + g_np2[t * 4 + 3];
    float d2 = n1 + n2 - 2.f * s;
    g_dist[e] = sqrtf(fmaxf(d2, 0.f));
}

__global__ __launch_bounds__(128)
void psd_partial_kernel() {  // grid (128, 8)
    int e = blockIdx.x * 128 + threadIdx.x;
    int y = blockIdx.y;
    float s = 0.f;
    #pragma unroll
    for (int p = 0; p < 16; p++)
        s += g_psd[(size_t)(y * 16 + p) * NPIX + e];
    g_ptmp[(size_t)y * NPIX + e] = s;
}

// Hermitian-pair recombination: avgpsd pieces from complex-packed transform.
__global__ __launch_bounds__(128)
void psd_final_kernel() {  // grid 128 (one block per natural col)
    __shared__ float sbuf[8];
    int t = threadIdx.x, lane = t & 31, warp = t >> 5;
    int col = blockIdx.x, p = t;
    int i = col * 128 + p;
    int kr = __brev((unsigned)p) >> 25;
    int pp = __brev((unsigned)((128 - kr) & 127)) >> 25;
    int ip = ((128 - col) & 127) * 128 + pp;
    float Ti = 0.f, Tp = 0.f;
    #pragma unroll
    for (int y = 0; y < 8; y++) {
        Ti += g_ptmp[(size_t)y * NPIX + i];
        Tp += g_ptmp[(size_t)y * NPIX + ip];
    }
    float avg = (Ti + Tp) * (0.5f / 256.f);
    float v1 = logf(avg), v2 = avg;
    #pragma unroll
    for (int o = 16; o; o >>= 1) {
        v1 += __shfl_xor_sync(0xffffffffu, v1, o);
        v2 += __shfl_xor_sync(0xffffffffu, v2, o);
    }
    if (lane == 0) { sbuf[warp] = v1; sbuf[4 + warp] = v2; }
    __syncthreads();
    if (t == 0) {
        g_redL[col] = sbuf[0] + sbuf[1] + sbuf[2] + sbuf[3];
        g_redA[col] = sbuf[4] + sbuf[5] + sbuf[6] + sbuf[7];
    }
}

__global__ __launch_bounds__(1024)
void final_kernel(float* __restrict__ out) {
    __shared__ float sbuf[32];
    int t = threadIdx.x, lane = t & 31, warp = t >> 5;
    float c = 0.f;
    #pragma unroll
    for (int rr = 0; rr < 4; rr++) {
        int row = warp * 4 + rr;
        const float* rp = g_dist + row * 128;
        float e0 = rp[lane], e1 = rp[lane + 32], e2 = rp[lane + 64], e3 = rp[lane + 96];
        float m = fmaxf(fmaxf(e0, e1), fmaxf(e2, e3));
        #pragma unroll
        for (int o = 16; o; o >>= 1) m = fmaxf(m, __shfl_xor_sync(0xffffffffu, m, o));
        float se = expf(e0 - m) + expf(e1 - m) + expf(e2 - m) + expf(e3 - m);
        #pragma unroll
        for (int o = 16; o; o >>= 1) se += __shfl_xor_sync(0xffffffffu, se, o);
        c += rp[row] - (m + logf(se));
    }
    if (lane == 0) sbuf[warp] = c;
    __syncthreads();
    if (t == 0) {
        float cs = 0.f;
        for (int w = 0; w < 32; w++) cs += sbuf[w];
        float ce = -cs / 128.f;
        float lsum = 0.f, asum = 0.f;
        for (int k = 0; k < 128; k++) { lsum += g_redL[k]; asum += g_redA[k]; }
        float r = lsum / 16384.f - logf(asum / 16384.f);
        out[0] = ce - 0.1f * r;
    }
}

// ---------------------------------------------------------------------------
extern "C" void kernel_launch(void* const* d_in, const int* in_sizes, int n_in,
                              void* d_out, int out_size) {
    const float* x1 = (const float*)d_in[0];
    const float* x2 = (const float*)d_in[1];
    float* out = (float*)d_out;

    const int SMEM_GRAM = 4 * 128 * SR;  // 73,728 B

    static cudaStream_t s1 = 0;
    static cudaEvent_t ev_fork, ev_row, ev_join;
    static bool inited = false;
    if (!inited) {
        cudaStreamCreateWithFlags(&s1, cudaStreamNonBlocking);
        cudaEventCreateWithFlags(&ev_fork, cudaEventDisableTiming);
        cudaEventCreateWithFlags(&ev_row, cudaEventDisableTiming);
        cudaEventCreateWithFlags(&ev_join, cudaEventDisableTiming);
        cudaFuncSetAttribute(gram_fused_kernel,
                             cudaFuncAttributeMaxDynamicSharedMemorySize, SMEM_GRAM);
        inited = true;
    }

    cudaEventRecord(ev_fork, 0);
    cudaStreamWaitEvent(s1, ev_fork, 0);

    // FFT / psd chain (legacy)
    fft_row_kernel<<<512, 256>>>(x1, x2);
    cudaEventRecord(ev_row, 0);  // g_np1/g_np2 + g_spec ready
    fft_col_kernel<<<512, 256>>>();
    psd_partial_kernel<<<dim3(128, 8), 128>>>();
    psd_final_kernel<<<128, 128>>>();

    // Gram chain (s1)
    gram_fused_kernel<<<128, 256, SMEM_GRAM, s1>>>(x1, x2);
    dist_partial_kernel<<<dim3(128, 8), 128, 0, s1>>>();
    cudaStreamWaitEvent(s1, ev_row, 0);  // needs norm partials
    dist_final_kernel<<<128, 128, 0, s1>>>();
    cudaEventRecord(ev_join, s1);

    cudaStreamWaitEvent(0, ev_join, 0);
    final_kernel<<<1, 1024>>>(out);
}

// round 10
// speedup vs baseline: 2.3921x; 1.0779x over previous
#include <cuda_runtime.h>
#include <cuda_bf16.h>
#include <cuda_fp16.h>
#include <math.h>
#include <stdint.h>

// OneClassLoss on GB300 — R6 (= R5 design + fixed CE lane-reduction bug).
//  legacy: fft_row (512 blk, half2 spec + norms) -> fft_col (256 blk, psd
//          accumulated over 8 pairs/block -> 16 partials) -> psd_sum
//  s1:     gram_fused (64 blk, K=256, bf16 hi/lo HMMA) -> dist_partial ->
//          [ev_row] dist_final
//  join:   final (Hermitian psd log-reduce + CE)
//
// BUGFIX vs R5: in final_kernel the CE accumulator c is warp-uniform (all 32
// lanes process the same rows); it must NOT be shfl-reduced across lanes
// (that multiplied ce by exactly 32 -> rel_err 31). Store from lane 0 only.

#define NPIX 16384

__device__ __half2 g_spec[128 * NPIX];     // row-FFT out, [pair][col][row] (8 MB)
__device__ float  g_psd_part[16 * NPIX];   // psd partials per pair-group (1 MB)
__device__ float  g_pavg[NPIX];            // summed psd (pre-Hermitian)
__device__ float  g_gram_part[64 * NPIX];  // partial Gram per K-chunk (4 MB)
__device__ float  g_dtmp[4 * NPIX];
__device__ float  g_np1[512], g_np2[512];  // norm partials (4 per image)
__device__ float  g_dist[NPIX];

// ---------------------------------------------------------------------------
// 128-pt DIF radix-2 complex FFT, one warp, 4 values/lane (n = r*32+lane).
// Output slot p holds bin rev7(p).
// ---------------------------------------------------------------------------
__device__ __forceinline__ void fft128(float vr[4], float vi[4],
                                       const float2* __restrict__ tw, int lane) {
    #pragma unroll
    for (int r = 0; r < 2; r++) {  // h=64
        float2 w = tw[r * 32 + lane];
        float ur = vr[r], ui = vi[r], xr = vr[r + 2], xi = vi[r + 2];
        vr[r] = ur + xr; vi[r] = ui + xi;
        float dr = ur - xr, di = ui - xi;
        vr[r + 2] = dr * w.x - di * w.y;
        vi[r + 2] = dr * w.y + di * w.x;
    }
    {  // h=32
        float2 w = tw[2 * lane];
        #pragma unroll
        for (int half = 0; half < 2; half++) {
            int r = half * 2;
            float ur = vr[r], ui = vi[r], xr = vr[r + 1], xi = vi[r + 1];
            vr[r] = ur + xr; vi[r] = ui + xi;
            float dr = ur - xr, di = ui - xi;
            vr[r + 1] = dr * w.x - di * w.y;
            vi[r + 1] = dr * w.y + di * w.x;
        }
    }
    #pragma unroll
    for (int st = 0; st < 5; st++) {  // h = 16,8,4,2,1
        const int h = 16 >> st;
        const int k = (lane & (h - 1)) * (64 / h);
        float2 w = tw[k];
        bool hiLane = (lane & h) != 0;
        #pragma unroll
        for (int r = 0; r < 4; r++) {
            float ar = vr[r], ai = vi[r];
            float br = __shfl_xor_sync(0xffffffffu, ar, h);
            float bi = __shfl_xor_sync(0xffffffffu, ai, h);
            if (hiLane) {
                float dr = br - ar, di = bi - ai;
                vr[r] = dr * w.x - di * w.y;
                vi[r] = dr * w.y + di * w.x;
            } else {
                vr[r] = ar + br;
                vi[r] = ai + bi;
            }
        }
    }
}

__device__ __forceinline__ void init_tw(float2* s_tw, int t) {
    if (t < 64) {
        float sn, cs;
        sincosf(-6.283185307179586f * (float)t / 128.0f, &sn, &cs);
        s_tw[t] = make_float2(cs, sn);
    }
}

// ---------------------------------------------------------------------------
// fft_row: grid 512 = 128 pairs x 4 row-groups of 32. z = x1 + i*x2.
// De-bitrev + transpose in smem; write half2 g_spec[pair][col][rows]. Norms.
// ---------------------------------------------------------------------------
__global__ __launch_bounds__(256)
void fft_row_kernel(const float* __restrict__ x1, const float* __restrict__ x2) {
    __shared__ float s_re[128 * 33], s_im[128 * 33];
    __shared__ float2 s_tw[64];
    __shared__ float s_red[16];

    int t = threadIdx.x, lane = t & 31, warp = t >> 5;  // 8 warps
    int b = blockIdx.x >> 2, rg = blockIdx.x & 3;
    const float* p1 = x1 + (size_t)b * NPIX;
    const float* p2 = x2 + (size_t)b * NPIX;

    init_tw(s_tw, t);
    __syncthreads();

    float n1 = 0.f, n2 = 0.f;
    #pragma unroll
    for (int q = 0; q < 4; q++) {
        int rl = warp * 4 + q;
        int row = rg * 32 + rl;
        float vr[4], vi[4];
        #pragma unroll
        for (int r = 0; r < 4; r++) {
            float xr = p1[row * 128 + r * 32 + lane];
            float xi = p2[row * 128 + r * 32 + lane];
            vr[r] = xr; vi[r] = xi;
            n1 += xr * xr; n2 += xi * xi;
        }
        fft128(vr, vi, s_tw, lane);
        #pragma unroll
        for (int r = 0; r < 4; r++) {
            int p = r * 32 + lane;
            int k = __brev((unsigned)p) >> 25;  // natural col bin
            s_re[k * 33 + rl] = vr[r];
            s_im[k * 33 + rl] = vi[r];
        }
    }

    #pragma unroll
    for (int o = 16; o; o >>= 1) {
        n1 += __shfl_xor_sync(0xffffffffu, n1, o);
        n2 += __shfl_xor_sync(0xffffffffu, n2, o);
    }
    if (lane == 0) { s_red[warp] = n1; s_red[8 + warp] = n2; }
    __syncthreads();
    if (t == 0) {
        float a = 0.f, c = 0.f;
        #pragma unroll
        for (int w = 0; w < 8; w++) { a += s_red[w]; c += s_red[8 + w]; }
        g_np1[blockIdx.x] = a; g_np2[blockIdx.x] = c;
    }

    __half2* spec = g_spec + (size_t)b * NPIX;
    #pragma unroll
    for (int it = 0; it < 16; it++) {
        int c = warp + it * 8;
        spec[c * 128 + rg * 32 + lane] =
            __floats2half2_rn(s_re[c * 33 + lane], s_im[c * 33 + lane]);
    }
}

// ---------------------------------------------------------------------------
// fft_col: grid 256 = 16 pair-groups x 16 col-groups. Warp w handles col
// cg*8+w, loops 8 pairs, accumulates |Z|^2 in regs -> g_psd_part[pg].
// ---------------------------------------------------------------------------
__global__ __launch_bounds__(256)
void fft_col_kernel() {
    __shared__ float2 s_tw[64];
    int t = threadIdx.x, lane = t & 31, warp = t >> 5;
    int pg = blockIdx.x >> 4, cg = blockIdx.x & 15;
    int col = cg * 8 + warp;
    init_tw(s_tw, t);
    __syncthreads();

    float acc[4] = {0.f, 0.f, 0.f, 0.f};
    #pragma unroll 2
    for (int q = 0; q < 8; q++) {
        int b = pg * 8 + q;
        const __half2* spec = g_spec + (size_t)b * NPIX + col * 128;
        float vr[4], vi[4];
        #pragma unroll
        for (int r = 0; r < 4; r++) {
            float2 z = __half22float2(spec[r * 32 + lane]);
            vr[r] = z.x; vi[r] = z.y;
        }
        fft128(vr, vi, s_tw, lane);
        #pragma unroll
        for (int r = 0; r < 4; r++)
            acc[r] += vr[r] * vr[r] + vi[r] * vi[r];
    }
    float* outp = g_psd_part + (size_t)pg * NPIX + col * 128;
    #pragma unroll
    for (int r = 0; r < 4; r++) outp[r * 32 + lane] = acc[r];
}

// ---------------------------------------------------------------------------
// psd_sum: grid 128 x 128 -> fully reduced g_pavg (16 partials, L2-resident).
// ---------------------------------------------------------------------------
__global__ __launch_bounds__(128)
void psd_sum_kernel() {
    int e = blockIdx.x * 128 + threadIdx.x;
    float s = 0.f;
    #pragma unroll
    for (int p = 0; p < 16; p++) s += g_psd_part[(size_t)p * NPIX + e];
    g_pavg[e] = s;
}

// ---------------------------------------------------------------------------
// gram_fused: 64 blocks, K-chunk 256 (4 stages of 64). fp32 load -> bf16
// hi/lo split in smem -> Ahi*Bhi + Ahi*Blo + Alo*Bhi HMMA accumulation.
// ---------------------------------------------------------------------------
__device__ __forceinline__ void ldsm4(uint32_t& r0, uint32_t& r1,
                                      uint32_t& r2, uint32_t& r3, uint32_t a) {
    asm volatile("ldmatrix.sync.aligned.m8n8.x4.shared.b16 {%0,%1,%2,%3}, [%4];"
                 : "=r"(r0), "=r"(r1), "=r"(r2), "=r"(r3) : "r"(a));
}
__device__ __forceinline__ void mma16816(float d[4], const uint32_t a[4],
                                         uint32_t b0, uint32_t b1) {
    asm volatile(
        "mma.sync.aligned.m16n8k16.row.col.f32.bf16.bf16.f32 "
        "{%0,%1,%2,%3}, {%4,%5,%6,%7}, {%8,%9}, {%0,%1,%2,%3};"
        : "+f"(d[0]), "+f"(d[1]), "+f"(d[2]), "+f"(d[3])
        : "r"(a[0]), "r"(a[1]), "r"(a[2]), "r"(a[3]), "r"(b0), "r"(b1));
}

#define SR 144  // smem row stride bytes (64 bf16 + pad)

__global__ __launch_bounds__(256, 2)
void gram_fused_kernel(const float* __restrict__ x1, const float* __restrict__ x2) {
    extern __shared__ char gsm[];
    char* sAhi = gsm;
    char* sAlo = gsm + 128 * SR;
    char* sBhi = gsm + 2 * 128 * SR;
    char* sBlo = gsm + 3 * 128 * SR;
    uint32_t uAhi = (uint32_t)__cvta_generic_to_shared(sAhi);
    uint32_t uAlo = (uint32_t)__cvta_generic_to_shared(sAlo);
    uint32_t uBhi = (uint32_t)__cvta_generic_to_shared(sBhi);
    uint32_t uBlo = (uint32_t)__cvta_generic_to_shared(sBlo);

    int t = threadIdx.x, lane = t & 31, ws = t >> 5;
    int k0 = blockIdx.x * 256;

    float acc[16][4];
    #pragma unroll
    for (int i = 0; i < 16; i++)
        #pragma unroll
        for (int j = 0; j < 4; j++) acc[i][j] = 0.f;

    uint32_t aOff = (ws * 16 + (lane & 15)) * SR + (lane >> 4) * 16;
    uint32_t bOff = ((lane & 7) + ((lane >> 4) << 3)) * SR + ((lane & 8) << 1);

    for (int stg = 0; stg < 4; stg++) {
        int ks = k0 + stg * 64;
        __syncthreads();
        #pragma unroll
        for (int c = 0; c < 8; c++) {
            int id = t + c * 256;
            int row = id >> 4, o = id & 15;
            float4 va = *(const float4*)(x1 + (size_t)row * NPIX + ks + o * 4);
            float4 vb = *(const float4*)(x2 + (size_t)row * NPIX + ks + o * 4);
            __nv_bfloat16 h0 = __float2bfloat16_rn(va.x), h1 = __float2bfloat16_rn(va.y);
            __nv_bfloat16 h2 = __float2bfloat16_rn(va.z), h3 = __float2bfloat16_rn(va.w);
            __nv_bfloat162 ahi0(h0, h1), ahi1(h2, h3);
            __nv_bfloat162 alo0(__float2bfloat16_rn(va.x - __bfloat162float(h0)),
                                __float2bfloat16_rn(va.y - __bfloat162float(h1)));
            __nv_bfloat162 alo1(__float2bfloat16_rn(va.z - __bfloat162float(h2)),
                                __float2bfloat16_rn(va.w - __bfloat162float(h3)));
            ((uint32_t*)(sAhi + row * SR + o * 8))[0] = *(uint32_t*)&ahi0;
            ((uint32_t*)(sAhi + row * SR + o * 8))[1] = *(uint32_t*)&ahi1;
            ((uint32_t*)(sAlo + row * SR + o * 8))[0] = *(uint32_t*)&alo0;
            ((uint32_t*)(sAlo + row * SR + o * 8))[1] = *(uint32_t*)&alo1;
            __nv_bfloat16 g0 = __float2bfloat16_rn(vb.x), g1 = __float2bfloat16_rn(vb.y);
            __nv_bfloat16 g2 = __float2bfloat16_rn(vb.z), g3 = __float2bfloat16_rn(vb.w);
            __nv_bfloat162 bhi0(g0, g1), bhi1(g2, g3);
            __nv_bfloat162 blo0(__float2bfloat16_rn(vb.x - __bfloat162float(g0)),
                                __float2bfloat16_rn(vb.y - __bfloat162float(g1)));
            __nv_bfloat162 blo1(__float2bfloat16_rn(vb.z - __bfloat162float(g2)),
                                __float2bfloat16_rn(vb.w - __bfloat162float(g3)));
            ((uint32_t*)(sBhi + row * SR + o * 8))[0] = *(uint32_t*)&bhi0;
            ((uint32_t*)(sBhi + row * SR + o * 8))[1] = *(uint32_t*)&bhi1;
            ((uint32_t*)(sBlo + row * SR + o * 8))[0] = *(uint32_t*)&blo0;
            ((uint32_t*)(sBlo + row * SR + o * 8))[1] = *(uint32_t*)&blo1;
        }
        __syncthreads();
        #pragma unroll
        for (int kk = 0; kk < 4; kk++) {
            uint32_t ah[4], al[4];
            ldsm4(ah[0], ah[1], ah[2], ah[3], uAhi + aOff + kk * 32);
            ldsm4(al[0], al[1], al[2], al[3], uAlo + aOff + kk * 32);
            #pragma unroll
            for (int j = 0; j < 8; j++) {
                uint32_t h0, h1, h2, h3, l0, l1, l2, l3;
                ldsm4(h0, h1, h2, h3, uBhi + bOff + j * 16 * SR + kk * 32);
                ldsm4(l0, l1, l2, l3, uBlo + bOff + j * 16 * SR + kk * 32);
                mma16816(acc[2 * j],     ah, h0, h1);
                mma16816(acc[2 * j + 1], ah, h2, h3);
                mma16816(acc[2 * j],     ah, l0, l1);
                mma16816(acc[2 * j + 1], ah, l2, l3);
                mma16816(acc[2 * j],     al, h0, h1);
                mma16816(acc[2 * j + 1], al, h2, h3);
            }
        }
    }

    float* out = g_gram_part + (size_t)blockIdx.x * NPIX;
    int g = lane >> 2, tt = lane & 3;
    #pragma unroll
    for (int i = 0; i < 16; i++) {
        int col = i * 8 + tt * 2;
        int r0 = ws * 16 + g;
        *(float2*)&out[r0 * 128 + col]       = make_float2(acc[i][0], acc[i][1]);
        *(float2*)&out[(r0 + 8) * 128 + col] = make_float2(acc[i][2], acc[i][3]);
    }
}

// ---------------------------------------------------------------------------
// dist reduce: 64 partials -> 4 -> Dist.
// ---------------------------------------------------------------------------
__global__ __launch_bounds__(128)
void dist_partial_kernel() {  // grid (128, 4)
    int e = blockIdx.x * 128 + threadIdx.x;
    int y = blockIdx.y;
    float s = 0.f;
    #pragma unroll
    for (int pp = 0; pp < 16; pp++)
        s += g_gram_part[(size_t)(y * 16 + pp) * NPIX + e];
    g_dtmp[(size_t)y * NPIX + e] = s;
}

__global__ __launch_bounds__(128)
void dist_final_kernel() {  // grid 128
    int bi = blockIdx.x, t = threadIdx.x;
    int e = bi * 128 + t;
    float s = g_dtmp[e] + g_dtmp[NPIX + e] + g_dtmp[2 * NPIX + e] + g_dtmp[3 * NPIX + e];
    float n1 = g_np1[bi * 4] + g_np1[bi * 4 + 1] + g_np1[bi * 4 + 2] + g_np1[bi * 4 + 3];
    float n2 = g_np2[t * 4] + g_np2[t * 4 + 1] + g_np2[t * 4 + 2] + g_np2[t * 4 + 3];
    float d2 = n1 + n2 - 2.f * s;
    g_dist[e] = sqrtf(fmaxf(d2, 0.f));
}

// ---------------------------------------------------------------------------
// final: Hermitian psd recombination + log reduce (64KB L2) + CE.
// v1/v2 are per-lane distinct -> lane-reduce. c is warp-uniform -> lane 0
// stores it directly (reducing it across lanes multiplies ce by 32!).
// ---------------------------------------------------------------------------
__global__ __launch_bounds__(1024)
void final_kernel(float* __restrict__ out) {
    __shared__ float sbufL[32], sbufA[32], sbufC[32];
    int t = threadIdx.x, lane = t & 31, warp = t >> 5;

    float v1 = 0.f, v2 = 0.f;
    #pragma unroll
    for (int q = 0; q < 16; q++) {
        int i = q * 1024 + t;
        int col = i >> 7, p = i & 127;
        int kr = __brev((unsigned)p) >> 25;
        int pp = __brev((unsigned)((128 - kr) & 127)) >> 25;
        int ip = ((128 - col) & 127) * 128 + pp;
        float avg = (g_pavg[i] + g_pavg[ip]) * (0.5f / 256.f);
        v1 += logf(avg);
        v2 += avg;
    }

    float c = 0.f;
    #pragma unroll
    for (int rr = 0; rr < 4; rr++) {
        int row = warp * 4 + rr;
        const float* rp = g_dist + row * 128;
        float e0 = rp[lane], e1 = rp[lane + 32], e2 = rp[lane + 64], e3 = rp[lane + 96];
        float m = fmaxf(fmaxf(e0, e1), fmaxf(e2, e3));
        #pragma unroll
        for (int o = 16; o; o >>= 1) m = fmaxf(m, __shfl_xor_sync(0xffffffffu, m, o));
        float se = expf(e0 - m) + expf(e1 - m) + expf(e2 - m) + expf(e3 - m);
        #pragma unroll
        for (int o = 16; o; o >>= 1) se += __shfl_xor_sync(0xffffffffu, se, o);
        c += rp[row] - (m + logf(se));  // warp-uniform
    }

    #pragma unroll
    for (int o = 16; o; o >>= 1) {      // lane-reduce ONLY v1/v2
        v1 += __shfl_xor_sync(0xffffffffu, v1, o);
        v2 += __shfl_xor_sync(0xffffffffu, v2, o);
    }
    if (lane == 0) { sbufL[warp] = v1; sbufA[warp] = v2; sbufC[warp] = c; }
    __syncthreads();
    if (t == 0) {
        float lsum = 0.f, asum = 0.f, cs = 0.f;
        #pragma unroll
        for (int w = 0; w < 32; w++) {
            lsum += sbufL[w]; asum += sbufA[w]; cs += sbufC[w];
        }
        float ce = -cs / 128.f;
        float r = lsum / 16384.f - logf(asum / 16384.f);
        out[0] = ce - 0.1f * r;
    }
}

// ---------------------------------------------------------------------------
extern "C" void kernel_launch(void* const* d_in, const int* in_sizes, int n_in,
                              void* d_out, int out_size) {
    const float* x1 = (const float*)d_in[0];
    const float* x2 = (const float*)d_in[1];
    float* out = (float*)d_out;

    const int SMEM_GRAM = 4 * 128 * SR;  // 73,728 B

    static cudaStream_t s1 = 0;
    static cudaEvent_t ev_fork, ev_row, ev_join;
    static bool inited = false;
    if (!inited) {
        cudaStreamCreateWithFlags(&s1, cudaStreamNonBlocking);
        cudaEventCreateWithFlags(&ev_fork, cudaEventDisableTiming);
        cudaEventCreateWithFlags(&ev_row, cudaEventDisableTiming);
        cudaEventCreateWithFlags(&ev_join, cudaEventDisableTiming);
        cudaFuncSetAttribute(gram_fused_kernel,
                             cudaFuncAttributeMaxDynamicSharedMemorySize, SMEM_GRAM);
        inited = true;
    }

    cudaEventRecord(ev_fork, 0);
    cudaStreamWaitEvent(s1, ev_fork, 0);

    // FFT / psd chain (legacy)
    fft_row_kernel<<<512, 256>>>(x1, x2);
    cudaEventRecord(ev_row, 0);  // norm partials + g_spec ready
    fft_col_kernel<<<256, 256>>>();
    psd_sum_kernel<<<128, 128>>>();

    // Gram chain (s1)
    gram_fused_kernel<<<64, 256, SMEM_GRAM, s1>>>(x1, x2);
    dist_partial_kernel<<<dim3(128, 4), 128, 0, s1>>>();
    cudaStreamWaitEvent(s1, ev_row, 0);
    dist_final_kernel<<<128, 128, 0, s1>>>();
    cudaEventRecord(ev_join, s1);

    cudaStreamWaitEvent(0, ev_join, 0);
    final_kernel<<<1, 1024>>>(out);
}